// round 3
// baseline (speedup 1.0000x reference)
#include <cuda_runtime.h>
#include <cstdint>

// Problem constants: x is (16384, 2048) fp32, angles (2048,) fp32, out (16384, 2048) fp32.
constexpr int NN = 2048;   // row length n
constexpr int T  = 256;    // threads per block
constexpr int E  = 8;      // elements per thread (T*E == NN)
constexpr int R  = 8;      // rows per block (coefficient reuse + load pipelining)

// Precomputed cos/sin (device globals: no dynamic allocation allowed).
__device__ __align__(16) float g_c[NN];
__device__ __align__(16) float g_s[NN];

__global__ void prep_kernel(const float* __restrict__ ang) {
    int i = blockIdx.x * blockDim.x + threadIdx.x;
    if (i < NN) {
        float s, c;
        sincosf(ang[i], &s, &c);
        g_c[i] = c;
        g_s[i] = s;
    }
}

// y_row = G_0 (G_1 (... (G_{N-1} x_row))).
// Rotations applied k = N-1 .. 0; G_k acts on (k, (k+1)%N). Reduced to a
// first-order affine recurrence on the carry `prev`, parallelized with an
// affine-map (P,Q) scan: warp shuffle scan + cross-warp smem prefix.
__global__ void __launch_bounds__(T) givens_kernel(const float* __restrict__ x,
                                                   float* __restrict__ y,
                                                   int rows) {
    __shared__ float wtP[2][8], wtQ[2][8];   // double-buffered warp totals (1 bar/row)

    const int t   = threadIdx.x;
    const int lid = t & 31;
    const int w   = t >> 5;
    const int lo  = t * E;
    const long base = (long)blockIdx.x * R;

    // ---- coefficients: loaded ONCE per block into registers ----
    float cc[E], ss[E];
    {
        float4 c0 = reinterpret_cast<const float4*>(g_c + lo)[0];
        float4 c1 = reinterpret_cast<const float4*>(g_c + lo)[1];
        cc[0] = c0.x; cc[1] = c0.y; cc[2] = c0.z; cc[3] = c0.w;
        cc[4] = c1.x; cc[5] = c1.y; cc[6] = c1.z; cc[7] = c1.w;
        float4 s0 = reinterpret_cast<const float4*>(g_s + lo)[0];
        float4 s1 = reinterpret_cast<const float4*>(g_s + lo)[1];
        ss[0] = s0.x; ss[1] = s0.y; ss[2] = s0.z; ss[3] = s0.w;
        ss[4] = s1.x; ss[5] = s1.y; ss[6] = s1.z; ss[7] = s1.w;
    }
    const float cN = g_c[NN - 1];
    const float sN = g_s[NN - 1];

    // Warp-head lanes (lane 0 of warps 1..7) rebuild their output carry from
    // the previous chunk's tail coefficients: out[lo] = s[lo-1]*x[lo-1] + c[lo-1]*prev_lo.
    const bool warp_head = (lid == 0) && (w > 0);
    float cprev = 0.f, sprev = 0.f;
    if (warp_head) { cprev = g_c[lo - 1]; sprev = g_s[lo - 1]; }

    // ---- prologue: loads for row 0 ----
    const float* __restrict__ xr0 = x + base * NN;
    float4 a0 = reinterpret_cast<const float4*>(xr0 + lo)[0];
    float4 a1 = reinterpret_cast<const float4*>(xr0 + lo)[1];
    float x0  = xr0[0];
    float xn1 = xr0[NN - 1];
    float xprev = warp_head ? xr0[lo - 1] : 0.f;

#pragma unroll 1
    for (int r = 0; r < R; ++r) {
        if (base + r >= rows) break;

        float xv[E];
        xv[0] = a0.x; xv[1] = a0.y; xv[2] = a0.z; xv[3] = a0.w;
        xv[4] = a1.x; xv[5] = a1.y; xv[6] = a1.z; xv[7] = a1.w;
        const float seed = fmaf(cN, xn1, -sN * x0);       // prev_{N-1}
        if (t == 0) xv[0] = fmaf(sN, xn1, cN * x0);       // X_0 = updated x[0]
        const float xpv = xprev;

        // ---- prefetch next row BEFORE the barrier (hide DRAM latency) ----
        if (r + 1 < R && base + r + 1 < rows) {
            const float* __restrict__ xr2 = x + (base + r + 1) * NN;
            a0 = reinterpret_cast<const float4*>(xr2 + lo)[0];
            a1 = reinterpret_cast<const float4*>(xr2 + lo)[1];
            x0 = xr2[0];
            xn1 = xr2[NN - 1];
            if (warp_head) xprev = xr2[lo - 1];
        }

        // ---- per-chunk affine composition (f_k(p) = -s_k p + c_k X_k), k descending ----
        float P = 1.f, Q = 0.f;
#pragma unroll
        for (int m = E - 1; m >= 0; --m) {
            if (lo + m == NN - 1) continue;               // k = N-1 is the seed
            const float sk = ss[m];
            Q = fmaf(-sk, Q, cc[m] * xv[m]);
            P = -sk * P;
        }

        // ---- warp-level inclusive scan (earlier = higher lane) ----
#pragma unroll
        for (int d = 1; d < 32; d <<= 1) {
            float p2 = __shfl_down_sync(0xffffffffu, P, d);
            float q2 = __shfl_down_sync(0xffffffffu, Q, d);
            if (lid + d < 32) {
                Q = fmaf(P, q2, Q);
                P = P * p2;
            }
        }
        const int buf = r & 1;
        if (lid == 0) { wtP[buf][w] = P; wtQ[buf][w] = Q; }
        // warp-internal exclusive map = inclusive of lane+1 (identity at lane 31)
        float Pe = __shfl_down_sync(0xffffffffu, P, 1);
        float Qe = __shfl_down_sync(0xffffffffu, Q, 1);
        if (lid == 31) { Pe = 1.f; Qe = 0.f; }
        __syncthreads();

        // prefix over later warps (w2 > w), innermost = warp 7
        float Pp = 1.f, Qp = 0.f;
        for (int w2 = 7; w2 > w; --w2) {
            const float pt = wtP[buf][w2], qt = wtQ[buf][w2];
            Qp = fmaf(pt, Qp, qt);
            Pp = pt * Pp;
        }
        float prev = fmaf(Pe * Pp, seed, fmaf(Pe, Qp, Qe)); // carry entering chunk top

        // ---- replay: rv[m] = out[lo+m+1]; ends with prev = prev_lo ----
        float rv[E];
        rv[E - 1] = 0.f;                                   // only thread T-1 skips m=E-1
#pragma unroll
        for (int m = E - 1; m >= 0; --m) {
            if (lo + m == NN - 1) continue;
            const float sk = ss[m], ck = cc[m], xm = xv[m];
            rv[m] = fmaf(sk, xm, ck * prev);
            prev  = fmaf(-sk, prev, ck * xm);
        }

        // out[lo]: lanes 1-31 take previous lane's rv[7] by shuffle; warp-head
        // lanes recompute it locally; thread 0 has it as prev_0.
        float carry = __shfl_up_sync(0xffffffffu, rv[E - 1], 1);
        if (t == 0)           carry = prev;
        else if (warp_head)   carry = fmaf(sprev, xpv, cprev * prev);

        float* __restrict__ yr = y + (base + r) * NN;
        float4 o0, o1;
        o0.x = carry; o0.y = rv[0]; o0.z = rv[1]; o0.w = rv[2];
        o1.x = rv[3]; o1.y = rv[4]; o1.z = rv[5]; o1.w = rv[6];
        reinterpret_cast<float4*>(yr + lo)[0] = o0;
        reinterpret_cast<float4*>(yr + lo)[1] = o1;
    }
}

extern "C" void kernel_launch(void* const* d_in, const int* in_sizes, int n_in,
                              void* d_out, int out_size) {
    const float* x   = (const float*)d_in[0];   // (B, N) fp32
    const float* ang = (const float*)d_in[1];   // (N,)  fp32
    float* y = (float*)d_out;                   // (B, N) fp32

    prep_kernel<<<(NN + 255) / 256, 256>>>(ang);

    const int rows   = out_size / NN;           // B = 16384
    const int blocks = (rows + R - 1) / R;      // 2048
    givens_kernel<<<blocks, T>>>(x, y, rows);
}

// round 4
// speedup vs baseline: 1.1323x; 1.1323x over previous
#include <cuda_runtime.h>
#include <cstdint>

// Problem constants: x is (16384, 2048) fp32, angles (2048,) fp32, out (16384, 2048) fp32.
constexpr int NN = 2048;   // row length n
constexpr int T  = 256;    // threads per block
constexpr int E  = 8;      // elements per thread (T*E == NN)
constexpr int R  = 4;      // rows per block (weight/coeff amortization)

// Precomputed tables (device globals: no dynamic allocation allowed).
__device__ __align__(16) float g_c[NN];
__device__ __align__(16) float g_s[NN];
// Row-independent scan weights (P-side of the affine scan, precomputed):
__device__ float g_W5[5][T];   // warp scan jump weights: Wd[t] = prod_{i<d} P_{t+i} (0 past warp end)
__device__ float g_Pe[T];      // warp-exclusive product: prod over lanes > lid (same warp)
__device__ float g_PfA[T];     // block-exclusive product: prod over all threads > t
__device__ float g_Pw[8];      // per-warp total products

__global__ void prep_kernel(const float* __restrict__ ang) {
    int i = blockIdx.x * blockDim.x + threadIdx.x;
    if (i < NN) {
        float s, c;
        sincosf(ang[i], &s, &c);
        g_c[i] = c;
        g_s[i] = s;
    }
}

// One block of T threads: derive every P-side constant of the scan once.
__global__ void prep2_kernel() {
    __shared__ float sP[T];
    const int t = threadIdx.x, lid = t & 31, w = t >> 5, lo = t * E;

    float P = 1.f;
#pragma unroll
    for (int m = E - 1; m >= 0; --m) {
        if (lo + m == NN - 1) continue;       // k = N-1 is the seed, not a scan step
        P *= -g_s[lo + m];
    }
    sP[t] = P;
    __syncthreads();

    // Hillis-Steele suffix-scan jump weights (include OWN P: prod_{i=0..d-1} sP[t+i]).
    int d = 1;
    for (int di = 0; di < 5; ++di, d <<= 1) {
        float wgt = 0.f;
        if (lid + d < 32) {
            wgt = 1.f;
            for (int i = 0; i < d; ++i) wgt *= sP[t + i];
        }
        g_W5[di][t] = wgt;
    }
    float Pe = 1.f;
    for (int l = lid + 1; l < 32; ++l) Pe *= sP[(w << 5) + l];
    g_Pe[t] = Pe;
    float Pf = Pe;
    for (int t2 = (w + 1) << 5; t2 < T; ++t2) Pf *= sP[t2];
    g_PfA[t] = Pf;
    if (t < 8) {
        float p = 1.f;
        for (int l = 0; l < 32; ++l) p *= sP[(t << 5) + l];
        g_Pw[t] = p;
    }
}

// y_row = G_0 (G_1 (... (G_{N-1} x_row))). First-order affine recurrence on the
// carry; Q-only weighted suffix scan per row (P-side precomputed).
__global__ void __launch_bounds__(T, 5) givens_kernel(const float* __restrict__ x,
                                                      float* __restrict__ y,
                                                      int rows) {
    __shared__ __align__(16) float wtQ[2][8];   // double-buffered warp Q-totals

    const int t   = threadIdx.x;
    const int lid = t & 31;
    const int w   = t >> 5;
    const int lo  = t * E;
    const long base = (long)blockIdx.x * R;

    // ---- per-block constants into registers ----
    float cc[E], ss[E];
    {
        float4 c0 = reinterpret_cast<const float4*>(g_c + lo)[0];
        float4 c1 = reinterpret_cast<const float4*>(g_c + lo)[1];
        cc[0] = c0.x; cc[1] = c0.y; cc[2] = c0.z; cc[3] = c0.w;
        cc[4] = c1.x; cc[5] = c1.y; cc[6] = c1.z; cc[7] = c1.w;
        float4 s0 = reinterpret_cast<const float4*>(g_s + lo)[0];
        float4 s1 = reinterpret_cast<const float4*>(g_s + lo)[1];
        ss[0] = s0.x; ss[1] = s0.y; ss[2] = s0.z; ss[3] = s0.w;
        ss[4] = s1.x; ss[5] = s1.y; ss[6] = s1.z; ss[7] = s1.w;
    }
    float W[5];
#pragma unroll
    for (int di = 0; di < 5; ++di) W[di] = g_W5[di][t];
    const float Pe = g_Pe[t];
    const float Pf = g_PfA[t];
    const float pw1 = g_Pw[1], pw2 = g_Pw[2], pw3 = g_Pw[3], pw4 = g_Pw[4],
                pw5 = g_Pw[5], pw6 = g_Pw[6], pw7 = g_Pw[7];
    const float cN = g_c[NN - 1];
    const float sN = g_s[NN - 1];

    // Warp-head lanes (lane 0 of warps 1..7) rebuild out[lo] locally:
    // out[lo] = s[lo-1]*x[lo-1] + c[lo-1]*prev_lo  (prev_lo = own replay carry).
    const bool warp_head = (lid == 0) && (w > 0);
    float cprev = 0.f, sprev = 0.f;
    if (warp_head) { cprev = g_c[lo - 1]; sprev = g_s[lo - 1]; }

#pragma unroll 1
    for (int r = 0; r < R; ++r) {
        if (base + r >= rows) break;
        const float* __restrict__ xr = x + (base + r) * NN;

        float xv[E];
        {
            float4 v0 = reinterpret_cast<const float4*>(xr + lo)[0];
            float4 v1 = reinterpret_cast<const float4*>(xr + lo)[1];
            xv[0] = v0.x; xv[1] = v0.y; xv[2] = v0.z; xv[3] = v0.w;
            xv[4] = v1.x; xv[5] = v1.y; xv[6] = v1.z; xv[7] = v1.w;
        }
        const float x0  = xr[0];
        const float xn1 = xr[NN - 1];
        const float xpv = warp_head ? xr[lo - 1] : 0.f;

        const float seed = fmaf(cN, xn1, -sN * x0);   // prev_{N-1}
        if (t == 0) xv[0] = fmaf(sN, xn1, cN * x0);   // X_0 = updated x[0]

        // ---- per-chunk Q composition (f_k(p) = -s_k p + c_k X_k), k descending ----
        float Q = 0.f;
#pragma unroll
        for (int m = E - 1; m >= 0; --m) {
            if (lo + m == NN - 1) continue;           // seed step
            Q = fmaf(-ss[m], Q, cc[m] * xv[m]);
        }

        // ---- Q-only weighted warp suffix scan (P-side precomputed) ----
#pragma unroll
        for (int di = 0, d = 1; di < 5; ++di, d <<= 1) {
            float q2 = __shfl_down_sync(0xffffffffu, Q, d);
            Q = fmaf(W[di], q2, Q);
        }
        float Qe = __shfl_down_sync(0xffffffffu, Q, 1);  // warp-exclusive Q
        if (lid == 31) Qe = 0.f;

        const int buf = r & 1;
        if (lid == 0) wtQ[buf][w] = Q;                   // warp total (lane 0 inclusive)
        __syncthreads();

        // cross-warp Horner over later warps (w2 = 7 .. w+1), Pw in registers
        float4 qa = *reinterpret_cast<const float4*>(&wtQ[buf][0]);
        float4 qb = *reinterpret_cast<const float4*>(&wtQ[buf][4]);
        float Qp = 0.f;
        if (w < 7) Qp = qb.w;
        if (w < 6) Qp = fmaf(pw6, Qp, qb.z);
        if (w < 5) Qp = fmaf(pw5, Qp, qb.y);
        if (w < 4) Qp = fmaf(pw4, Qp, qb.x);
        if (w < 3) Qp = fmaf(pw3, Qp, qa.w);
        if (w < 2) Qp = fmaf(pw2, Qp, qa.z);
        if (w < 1) Qp = fmaf(pw1, Qp, qa.y);
        (void)pw7;

        float prev = fmaf(Pf, seed, fmaf(Pe, Qp, Qe));   // carry entering chunk top

        // ---- replay in place: xv[m] <- out[lo+m+1]; ends with prev = prev_lo ----
#pragma unroll
        for (int m = E - 1; m >= 0; --m) {
            if (lo + m == NN - 1) { xv[m] = 0.f; continue; }
            const float xm = xv[m];
            xv[m] = fmaf(ss[m], xm, cc[m] * prev);
            prev  = fmaf(-ss[m], prev, cc[m] * xm);
        }

        // out[lo]: lanes 1-31 take previous lane's xv[7]; warp heads recompute;
        // thread 0 has it as prev_0.
        float carry = __shfl_up_sync(0xffffffffu, xv[E - 1], 1);
        if (t == 0)         carry = prev;
        else if (warp_head) carry = fmaf(sprev, xpv, cprev * prev);

        float* __restrict__ yr = y + (base + r) * NN;
        float4 o0, o1;
        o0.x = carry; o0.y = xv[0]; o0.z = xv[1]; o0.w = xv[2];
        o1.x = xv[3]; o1.y = xv[4]; o1.z = xv[5]; o1.w = xv[6];
        reinterpret_cast<float4*>(yr + lo)[0] = o0;
        reinterpret_cast<float4*>(yr + lo)[1] = o1;
    }
}

extern "C" void kernel_launch(void* const* d_in, const int* in_sizes, int n_in,
                              void* d_out, int out_size) {
    const float* x   = (const float*)d_in[0];   // (B, N) fp32
    const float* ang = (const float*)d_in[1];   // (N,)  fp32
    float* y = (float*)d_out;                   // (B, N) fp32

    prep_kernel<<<(NN + 255) / 256, 256>>>(ang);
    prep2_kernel<<<1, T>>>();

    const int rows   = out_size / NN;           // B = 16384
    const int blocks = (rows + R - 1) / R;      // 4096
    givens_kernel<<<blocks, T>>>(x, y, rows);
}